// round 1
// baseline (speedup 1.0000x reference)
#include <cuda_runtime.h>

// Radon forward projection matching the JAX reference:
//   image (2,1,256,256) f32 -> sinogram (2,1,363,180) f32
// S = 363, padded image region occupies padded coords [53, 309) in both axes.
// px(i,j) = cos*(j-181) + sin*(i-181) + 181 ; py(i,j) = -sin*(j-181) + cos*(i-181) + 181
// out[b,0,j,t] = sum_i bilinear(padded_img_b, py(i,j), px(i,j))

namespace {
constexpr int   kS = 363;
constexpr int   kT = 180;
constexpr float kMagic = 8388608.0f;   // 2^23
}

__global__ void __launch_bounds__(128) radon_fwd(const float* __restrict__ img,
                                                 float* __restrict__ out)
{
    const int j = blockIdx.x * blockDim.x + threadIdx.x;
    const int t = blockIdx.y;
    if (j >= kS) return;

    const float theta = (float)t * (180.0f / 179.0f) * 0.017453292519943295f;
    float s, c;
    sincosf(theta, &s, &c);

    const float fj = (float)j - 181.0f;
    // px(i) = px_base + s*i ; py(i) = py_base + c*i
    const float px_base = fmaf(c, fj, fmaf(-181.0f, s, 181.0f));
    const float py_base = fmaf(-s, fj, fmaf(-181.0f, c, 181.0f));

    // ---- outer clip: i-range where any tap can be nonzero (px,py in (52,309)) ----
    float lo = 0.0f, hi = 362.0f;
    bool empty = false;
    {
        float d = s, b = px_base;
        #pragma unroll
        for (int axis = 0; axis < 2; ++axis) {
            if (fabsf(d) < 1e-7f) {
                if (b <= 52.0f || b >= 309.0f) empty = true;
            } else {
                float t0 = (52.0f  - b) / d;
                float t1 = (309.0f - b) / d;
                lo = fmaxf(lo, fminf(t0, t1));
                hi = fminf(hi, fmaxf(t0, t1));
            }
            d = c; b = py_base;
        }
    }
    lo = fmaxf(lo, 0.0f);
    hi = fminf(hi, 362.0f);

    int i_lo = 0, i_hi = -1;
    if (!empty && lo <= hi + 1.0f) {
        i_lo = max(0,   (int)floorf(lo) - 1);
        i_hi = min(362, (int)ceilf(hi) + 1);
    }

    // ---- interior clip: all 4 taps strictly inside image (px,py in [53,308)) ----
    int in_lo = i_hi + 1, in_hi = i_hi;   // default: empty interior
    if (i_lo <= i_hi) {
        float lo2 = (float)i_lo, hi2 = (float)i_hi;
        bool iempty = false;
        float d = s, b = px_base;
        #pragma unroll
        for (int axis = 0; axis < 2; ++axis) {
            if (fabsf(d) < 1e-7f) {
                if (b < 53.0f || b >= 308.0f) iempty = true;
            } else {
                float t0 = (53.0f   - b) / d;
                float t1 = (307.99f - b) / d;
                lo2 = fmaxf(lo2, fminf(t0, t1));
                hi2 = fminf(hi2, fmaxf(t0, t1));
            }
            d = c; b = py_base;
        }
        if (!iempty) {
            lo2 = fmaxf(lo2, 0.0f);
            hi2 = fminf(hi2, 362.0f);
            in_lo = max((int)ceilf(lo2),  i_lo);
            in_hi = min((int)floorf(hi2), i_hi);
            // exact verification (linear => endpoints inside <=> whole range inside)
            while (in_lo <= in_hi) {
                float px = fmaf(s, (float)in_lo, px_base);
                float py = fmaf(c, (float)in_lo, py_base);
                if (px >= 53.0f && px < 308.0f && py >= 53.0f && py < 308.0f) break;
                ++in_lo;
            }
            while (in_hi >= in_lo) {
                float px = fmaf(s, (float)in_hi, px_base);
                float py = fmaf(c, (float)in_hi, py_base);
                if (px >= 53.0f && px < 308.0f && py >= 53.0f && py < 308.0f) break;
                --in_hi;
            }
            if (in_lo > in_hi) { in_lo = i_hi + 1; in_hi = i_hi; }
        }
    }

    float acc0 = 0.0f, acc1 = 0.0f;

    auto sample_checked = [&](int i) {
        float fi = (float)i;
        float px = fmaf(s, fi, px_base);
        float py = fmaf(c, fi, py_base);
        float xf = floorf(px), yf = floorf(py);
        int   x0 = (int)xf,    y0 = (int)yf;
        float wx1 = px - xf,   wy1 = py - yf;
        float wx0 = 1.0f - wx1, wy0 = 1.0f - wy1;
        int xi0 = x0 - 53, yi0 = y0 - 53;
        bool vx0 = (unsigned)xi0       < 256u;
        bool vx1 = (unsigned)(xi0 + 1) < 256u;
        bool vy0 = (unsigned)yi0       < 256u;
        bool vy1 = (unsigned)(yi0 + 1) < 256u;
        int base = yi0 * 256 + xi0;
        float w00 = wy0 * wx0, w01 = wy0 * wx1;
        float w10 = wy1 * wx0, w11 = wy1 * wx1;
        if (vy0 && vx0) { acc0 = fmaf(img[base],           w00, acc0); acc1 = fmaf(img[base + 65536],       w00, acc1); }
        if (vy0 && vx1) { acc0 = fmaf(img[base + 1],       w01, acc0); acc1 = fmaf(img[base + 65537],       w01, acc1); }
        if (vy1 && vx0) { acc0 = fmaf(img[base + 256],     w10, acc0); acc1 = fmaf(img[base + 65536 + 256], w10, acc1); }
        if (vy1 && vx1) { acc0 = fmaf(img[base + 257],     w11, acc0); acc1 = fmaf(img[base + 65536 + 257], w11, acc1); }
    };

    for (int i = i_lo; i < in_lo; ++i) sample_checked(i);

    #pragma unroll 4
    for (int i = in_lo; i <= in_hi; ++i) {
        float fi = (float)i;
        float px = fmaf(s, fi, px_base);
        float py = fmaf(c, fi, py_base);
        // floor via round-toward-zero magic add (px,py >= 53 here)
        float fx = __fadd_rz(px, kMagic);
        float fy = __fadd_rz(py, kMagic);
        float xf = fx - kMagic, yf = fy - kMagic;
        float wx1 = px - xf, wy1 = py - yf;
        float wx0 = 1.0f - wx1, wy0 = 1.0f - wy1;
        unsigned xb = __float_as_uint(fx);
        unsigned yb = __float_as_uint(fy);
        // off = (y0-53)*256 + (x0-53); 0x4B000000*256 == 0 (mod 2^32) folds the bias:
        int off = (int)(yb * 256u + xb + 0xB4FFCACBu);
        const float* p = img + off;
        float v00 = p[0],     v01 = p[1];
        float v10 = p[256],   v11 = p[257];
        float u00 = p[65536], u01 = p[65537];
        float u10 = p[65792], u11 = p[65793];
        float h0 = fmaf(wx1, v01, wx0 * v00);
        float h1 = fmaf(wx1, v11, wx0 * v10);
        acc0 = fmaf(wy0, h0, acc0);
        acc0 = fmaf(wy1, h1, acc0);
        float g0 = fmaf(wx1, u01, wx0 * u00);
        float g1 = fmaf(wx1, u11, wx0 * u10);
        acc1 = fmaf(wy0, g0, acc1);
        acc1 = fmaf(wy1, g1, acc1);
    }

    for (int i = in_hi + 1; i <= i_hi; ++i) sample_checked(i);

    // out shape (2,1,363,180): out[b,0,j,t]
    out[(0 * kS + j) * kT + t] = acc0;
    out[(1 * kS + j) * kT + t] = acc1;
}

extern "C" void kernel_launch(void* const* d_in, const int* in_sizes, int n_in,
                              void* d_out, int out_size)
{
    const float* img = (const float*)d_in[0];
    float* out = (float*)d_out;
    dim3 grid((kS + 127) / 128, kT);
    radon_fwd<<<grid, 128>>>(img, out);
}

// round 3
// speedup vs baseline: 2.3263x; 2.3263x over previous
#include <cuda_runtime.h>

// Radon forward projection:
//   image (2,1,256,256) f32 -> sinogram (2,1,363,180) f32
// S=363; padded image region = padded coords [53,309).
// px(i,j) = c*(j-181) + s*(i-181) + 181 ; py(i,j) = -s*(j-181) + c*(i-181) + 181
// out[b,0,j,t] = sum_i bilinear(padded_img_b, py, px)
//
// Round-1 layout: warp = (J x I) patch over (j, i-phase), J*I=32, (J,I) chosen
// per angle to minimize image-row span => fewer L1tex wavefronts per LDG.
// Block = 128 threads covering 16 j-values x 8 i-phases; smem reduction.

namespace {
constexpr int   kS = 363;
constexpr int   kT = 180;
constexpr float kMagic = 8388608.0f;   // 2^23
}

__global__ void __launch_bounds__(128) radon_fwd(const float* __restrict__ img,
                                                 float* __restrict__ out)
{
    const int t    = threadIdx.x;
    const int th   = blockIdx.y;              // angle index
    const int jbase = blockIdx.x * 16;

    const float theta = (float)th * (180.0f / 179.0f) * 0.017453292519943295f;
    float s, c;
    sincosf(theta, &s, &c);
    const float as = fabsf(s), ac = fabsf(c);

    // pick warp patch shape minimizing row-span J*|s| + I*|c|
    const float span0 = 16.f * as + 2.f * ac;   // (J,I)=(16,2)
    const float span1 =  8.f * as + 4.f * ac;   // (8,4)
    const float span2 =  4.f * as + 8.f * ac;   // (4,8)
    int jl, io;
    if (span0 <= span1 && span0 <= span2) {
        jl = t & 15;  io = t >> 4;
    } else if (span1 <= span2) {
        const int w = t >> 5;
        jl = (t & 7) | ((w & 1) << 3);
        io = ((t >> 3) & 3) | ((w >> 1) << 2);
    } else {
        const int w = t >> 5;
        io = t & 7;
        jl = ((t >> 3) & 3) | (w << 2);
    }

    const int j = jbase + jl;

    const float fj = (float)j - 181.0f;
    const float px_base = fmaf(c, fj, fmaf(-181.0f, s, 181.0f));
    const float py_base = fmaf(-s, fj, fmaf(-181.0f, c, 181.0f));

    // ---- outer clip: i-range where any tap can be nonzero ----
    float lo = 0.0f, hi = 362.0f;
    bool empty = (j >= kS);
    {
        float d = s, b = px_base;
        #pragma unroll
        for (int axis = 0; axis < 2; ++axis) {
            if (fabsf(d) < 1e-7f) {
                if (b <= 52.0f || b >= 309.0f) empty = true;
            } else {
                float t0 = (52.0f  - b) / d;
                float t1 = (309.0f - b) / d;
                lo = fmaxf(lo, fminf(t0, t1));
                hi = fminf(hi, fmaxf(t0, t1));
            }
            d = c; b = py_base;
        }
    }
    lo = fmaxf(lo, 0.0f);
    hi = fminf(hi, 362.0f);

    int i_lo = 0, i_hi = -1;
    if (!empty && lo <= hi + 1.0f) {
        i_lo = max(0,   (int)floorf(lo) - 1);
        i_hi = min(362, (int)ceilf(hi) + 1);
    }

    // ---- interior clip: all 4 taps strictly inside image ----
    int in_lo = i_hi + 1, in_hi = i_hi;
    if (i_lo <= i_hi) {
        float lo2 = (float)i_lo, hi2 = (float)i_hi;
        bool iempty = false;
        float d = s, b = px_base;
        #pragma unroll
        for (int axis = 0; axis < 2; ++axis) {
            if (fabsf(d) < 1e-7f) {
                if (b < 53.0f || b >= 308.0f) iempty = true;
            } else {
                float t0 = (53.0f   - b) / d;
                float t1 = (307.99f - b) / d;
                lo2 = fmaxf(lo2, fminf(t0, t1));
                hi2 = fminf(hi2, fmaxf(t0, t1));
            }
            d = c; b = py_base;
        }
        if (!iempty) {
            lo2 = fmaxf(lo2, 0.0f);
            hi2 = fminf(hi2, 362.0f);
            in_lo = max((int)ceilf(lo2),  i_lo);
            in_hi = min((int)floorf(hi2), i_hi);
            while (in_lo <= in_hi) {
                float px = fmaf(s, (float)in_lo, px_base);
                float py = fmaf(c, (float)in_lo, py_base);
                if (px >= 53.0f && px < 308.0f && py >= 53.0f && py < 308.0f) break;
                ++in_lo;
            }
            while (in_hi >= in_lo) {
                float px = fmaf(s, (float)in_hi, px_base);
                float py = fmaf(c, (float)in_hi, py_base);
                if (px >= 53.0f && px < 308.0f && py >= 53.0f && py < 308.0f) break;
                --in_hi;
            }
            if (in_lo > in_hi) { in_lo = i_hi + 1; in_hi = i_hi; }
        }
    }

    float acc0 = 0.0f, acc1 = 0.0f;

    auto sample_checked = [&](int i) {
        float fi = (float)i;
        float px = fmaf(s, fi, px_base);
        float py = fmaf(c, fi, py_base);
        float xf = floorf(px), yf = floorf(py);
        int   x0 = (int)xf,    y0 = (int)yf;
        float wx1 = px - xf,   wy1 = py - yf;
        float wx0 = 1.0f - wx1, wy0 = 1.0f - wy1;
        int xi0 = x0 - 53, yi0 = y0 - 53;
        bool vx0 = (unsigned)xi0       < 256u;
        bool vx1 = (unsigned)(xi0 + 1) < 256u;
        bool vy0 = (unsigned)yi0       < 256u;
        bool vy1 = (unsigned)(yi0 + 1) < 256u;
        int base = yi0 * 256 + xi0;
        float w00 = wy0 * wx0, w01 = wy0 * wx1;
        float w10 = wy1 * wx0, w11 = wy1 * wx1;
        if (vy0 && vx0) { acc0 = fmaf(img[base],           w00, acc0); acc1 = fmaf(img[base + 65536],       w00, acc1); }
        if (vy0 && vx1) { acc0 = fmaf(img[base + 1],       w01, acc0); acc1 = fmaf(img[base + 65537],       w01, acc1); }
        if (vy1 && vx0) { acc0 = fmaf(img[base + 256],     w10, acc0); acc1 = fmaf(img[base + 65536 + 256], w10, acc1); }
        if (vy1 && vx1) { acc0 = fmaf(img[base + 257],     w11, acc0); acc1 = fmaf(img[base + 65536 + 257], w11, acc1); }
    };

    // strided loop: this thread owns i-phase `io`, stride 8
    const int i0 = i_lo + ((io - i_lo) & 7);
    for (int i = i0; i <= i_hi; i += 8) {
        if (i >= in_lo && i <= in_hi) {
            float fi = (float)i;
            float px = fmaf(s, fi, px_base);
            float py = fmaf(c, fi, py_base);
            float fx = __fadd_rz(px, kMagic);
            float fy = __fadd_rz(py, kMagic);
            float xf = fx - kMagic, yf = fy - kMagic;
            float wx1 = px - xf, wy1 = py - yf;
            float wx0 = 1.0f - wx1, wy0 = 1.0f - wy1;
            unsigned xb = __float_as_uint(fx);
            unsigned yb = __float_as_uint(fy);
            // off = (y0-53)*256 + (x0-53); 0x4B000000*256 == 0 (mod 2^32):
            int off = (int)(yb * 256u + xb + 0xB4FFCACBu);
            const float* p = img + off;
            float v00 = p[0],     v01 = p[1];
            float v10 = p[256],   v11 = p[257];
            float u00 = p[65536], u01 = p[65537];
            float u10 = p[65792], u11 = p[65793];
            float h0 = fmaf(wx1, v01, wx0 * v00);
            float h1 = fmaf(wx1, v11, wx0 * v10);
            acc0 = fmaf(wy0, h0, acc0);
            acc0 = fmaf(wy1, h1, acc0);
            float g0 = fmaf(wx1, u01, wx0 * u00);
            float g1 = fmaf(wx1, u11, wx0 * u10);
            acc1 = fmaf(wy0, g0, acc1);
            acc1 = fmaf(wy1, g1, acc1);
        } else {
            sample_checked(i);
        }
    }

    // ---- reduction over the 8 i-phases via smem ----
    __shared__ float red[2][16][9];   // pad to 9 to avoid bank conflicts
    red[0][jl][io] = acc0;
    red[1][jl][io] = acc1;
    __syncthreads();

    if (t < 32) {
        const int b  = t >> 4;
        const int jj = t & 15;
        float sum = 0.0f;
        #pragma unroll
        for (int k = 0; k < 8; ++k) sum += red[b][jj][k];
        const int jo = jbase + jj;
        if (jo < kS) out[(b * kS + jo) * kT + th] = sum;
    }
}

extern "C" void kernel_launch(void* const* d_in, const int* in_sizes, int n_in,
                              void* d_out, int out_size)
{
    const float* img = (const float*)d_in[0];
    float* out = (float*)d_out;
    dim3 grid((kS + 15) / 16, kT);
    radon_fwd<<<grid, 128>>>(img, out);
}